// round 6
// baseline (speedup 1.0000x reference)
#include <cuda_runtime.h>
#include <math.h>

// ---------------------------------------------------------------------------
// PINN phase-field fracture residual losses on GB300 (sm_103a).
//
// Per point (x1,x2,t): forward MLP 3->128->128->128->3 (tanh) with
// forward-mode tangents along (x1, x2, t) and forward-over-forward second
// tangents along (x1x1, x1x2, x2x2). 7 vectors of width 128 per point.
//
// Mainloop: packed fma.rn.f32x2 (SASS FFMA2) with K-PAIR packing:
//   acc[v][m] = (sum over even k, sum over odd k) for channel j = lane+32m.
//   V operand  = (V[k],V[k+1])     <- broadcast LDS.128, no MOV packs
//   W operand  = (W[k,j],W[k+1,j]) <- TRANSPOSED weights in smem, LDS.64
// Transposed row stride 130 floats -> 8B-aligned, conflict-free LDS.64.
// Final cross-block reduction by last block (atomic ticket), single launch.
// ---------------------------------------------------------------------------

namespace {
constexpr int N_PTS   = 8192;
constexpr int HID     = 128;
constexpr int NVEC    = 7;       // h, d1, d2, dt, s11, s12, s22
constexpr int NBLK    = 148;     // one CTA per SM
constexpr int NWARP   = 16;
constexpr int NTHREADS = NWARP * 32;
constexpr int NWARP_TOT = NBLK * NWARP;  // 2368

constexpr int RSTR   = 130;      // transposed weight row stride (floats)
constexpr int WT_SZ  = HID * RSTR;  // 16640 floats per layer

constexpr float MU_  = 80.77f;
constexpr float LAM_ = 121.15f;
constexpr float GC_  = 2.7e-3f;
constexpr float LEN_ = 0.015f;

constexpr int SMEM_FLOATS = 2 * WT_SZ + NWARP * NVEC * HID;  // 47616
constexpr int SMEM_BYTES  = SMEM_FLOATS * 4;                 // 190464
}

__device__ float g_partials[NBLK * 3];
__device__ unsigned int g_ticket;   // zero-init; reset by last block each call

__device__ __forceinline__ void fma2(unsigned long long& d,
                                     unsigned long long a, unsigned long long b) {
    asm("fma.rn.f32x2 %0, %1, %2, %0;" : "+l"(d) : "l"(a), "l"(b));
}
__device__ __forceinline__ float2 unpack2(unsigned long long v) {
    float2 r;
    asm("mov.b64 {%0, %1}, %2;" : "=f"(r.x), "=f"(r.y) : "l"(v));
    return r;
}

__global__ void __launch_bounds__(NTHREADS, 1)
pinn_main(const float* __restrict__ x,  const float* __restrict__ t,
          const float* __restrict__ W0, const float* __restrict__ b0,
          const float* __restrict__ W1, const float* __restrict__ b1,
          const float* __restrict__ W2, const float* __restrict__ b2,
          const float* __restrict__ W3, const float* __restrict__ b3,
          float* __restrict__ out)
{
    extern __shared__ float smem[];
    float* Wsh  = smem;                  // [2][128*130] transposed
    float* Vall = smem + 2 * WT_SZ;      // [NWARP][NVEC][128]
    __shared__ float red[NWARP][3];
    __shared__ unsigned int s_last;

    // Transpose hidden-layer weights into SMEM: Wt[j*RSTR + k] = W[k*HID + j].
    for (int idx = threadIdx.x; idx < HID * HID; idx += NTHREADS) {
        const int k = idx >> 7;
        const int j = idx & 127;
        Wsh[j * RSTR + k]         = W1[idx];
        Wsh[WT_SZ + j * RSTR + k] = W2[idx];
    }
    __syncthreads();

    const int warp = threadIdx.x >> 5;
    const int lane = threadIdx.x & 31;
    float* V = Vall + warp * (NVEC * HID);

    // joff[m]: float2-index of row (lane+32m) in the transposed layout.
    int joff[4];
    #pragma unroll
    for (int m = 0; m < 4; m++) joff[m] = (lane + 32 * m) * (RSTR / 2);

    float w3r[4][3];
    #pragma unroll
    for (int m = 0; m < 4; m++) {
        const int k = lane + 32 * m;
        w3r[m][0] = W3[k * 3 + 0];
        w3r[m][1] = W3[k * 3 + 1];
        w3r[m][2] = W3[k * 3 + 2];
    }
    const float b30 = b3[0];

    float lsS = 0.f, lsP = 0.f, lsI = 0.f;

    // Transposed warp->point map: extra points spread across all SMs/SMSPs.
    const int wg = blockIdx.x + NBLK * warp;

    for (int p = wg; p < N_PTS; p += NWARP_TOT) {
        const float x1 = x[2 * p + 0];
        const float x2 = x[2 * p + 1];
        const float tt = t[p];

        __syncwarp();  // previous iteration's V reads done before overwrite

        // ---------------- layer 0 (3 -> 128), input is linear in coords ----
        #pragma unroll
        for (int m = 0; m < 4; m++) {
            const int j  = lane + 32 * m;
            const float a0 = W0[0 * HID + j];
            const float a1 = W0[1 * HID + j];
            const float a2 = W0[2 * HID + j];
            const float z  = fmaf(x1, a0, fmaf(x2, a1, fmaf(tt, a2, b0[j])));
            const float h  = tanhf(z);
            const float g  = 1.f - h * h;
            const float m2 = -2.f * h * g;
            V[0 * HID + j] = h;
            V[1 * HID + j] = g * a0;       // d/dx1
            V[2 * HID + j] = g * a1;       // d/dx2
            V[3 * HID + j] = g * a2;       // d/dt
            V[4 * HID + j] = m2 * a0 * a0; // d2/dx1dx1
            V[5 * HID + j] = m2 * a0 * a1; // d2/dx1dx2
            V[6 * HID + j] = m2 * a1 * a1; // d2/dx2dx2
        }
        __syncwarp();

        // ---------------- hidden layers 1 & 2 (128 -> 128) ------------------
        #pragma unroll
        for (int L = 0; L < 2; L++) {
            const unsigned long long* Wll =
                reinterpret_cast<const unsigned long long*>(Wsh + L * WT_SZ);

            unsigned long long acc[NVEC][4];
            #pragma unroll
            for (int v = 0; v < NVEC; v++)
                #pragma unroll
                for (int m = 0; m < 4; m++) acc[v][m] = 0ull;

            #pragma unroll 2
            for (int k = 0; k < HID; k += 4) {
                // Weight k-pairs for 4 channels: conflict-free LDS.64.
                unsigned long long wA[4], wB[4];
                #pragma unroll
                for (int m = 0; m < 4; m++) {
                    wA[m] = Wll[joff[m] + (k >> 1)];
                    wB[m] = Wll[joff[m] + (k >> 1) + 1];
                }
                const float* Vk = V + k;
                #pragma unroll
                for (int v = 0; v < NVEC; v++) {
                    // (V[k],V[k+1]),(V[k+2],V[k+3]) via one broadcast LDS.128.
                    const ulonglong2 vv =
                        *reinterpret_cast<const ulonglong2*>(Vk + v * HID);
                    #pragma unroll
                    for (int m = 0; m < 4; m++) {
                        fma2(acc[v][m], vv.x, wA[m]);
                        fma2(acc[v][m], vv.y, wB[m]);
                    }
                }
            }

            // Collapse k-split halves.
            float accf[NVEC][4];
            #pragma unroll
            for (int v = 0; v < NVEC; v++)
                #pragma unroll
                for (int m = 0; m < 4; m++) {
                    const float2 a = unpack2(acc[v][m]);
                    accf[v][m] = a.x + a.y;
                }

            const float* bias = (L == 0) ? b1 : b2;
            __syncwarp();  // everyone done reading V for this layer
            #pragma unroll
            for (int m = 0; m < 4; m++) {
                const int j = lane + 32 * m;
                const float zh  = accf[0][m] + bias[j];
                const float h   = tanhf(zh);
                const float g   = 1.f - h * h;
                const float zd1 = accf[1][m];
                const float zd2 = accf[2][m];
                const float zdt = accf[3][m];
                const float m2  = -2.f * h * g;
                V[0 * HID + j] = h;
                V[1 * HID + j] = g * zd1;
                V[2 * HID + j] = g * zd2;
                V[3 * HID + j] = g * zdt;
                V[4 * HID + j] = fmaf(m2 * zd1, zd1, g * accf[4][m]);
                V[5 * HID + j] = fmaf(m2 * zd1, zd2, g * accf[5][m]);
                V[6 * HID + j] = fmaf(m2 * zd2, zd2, g * accf[6][m]);
            }
            __syncwarp();
        }

        // ---------------- output layer (128 -> 3) + warp reduction ----------
        float S[NVEC][3];
        #pragma unroll
        for (int v = 0; v < NVEC; v++)
            S[v][0] = S[v][1] = S[v][2] = 0.f;

        #pragma unroll
        for (int m = 0; m < 4; m++) {
            const int k = lane + 32 * m;
            #pragma unroll
            for (int v = 0; v < NVEC; v++) {
                const float vk = V[v * HID + k];
                S[v][0] = fmaf(vk, w3r[m][0], S[v][0]);
                S[v][1] = fmaf(vk, w3r[m][1], S[v][1]);
                S[v][2] = fmaf(vk, w3r[m][2], S[v][2]);
            }
        }
        #pragma unroll
        for (int v = 0; v < NVEC; v++)
            #pragma unroll
            for (int o = 0; o < 3; o++)
                #pragma unroll
                for (int off = 16; off > 0; off >>= 1)
                    S[v][o] += __shfl_xor_sync(0xFFFFFFFFu, S[v][o], off);

        // ---------------- physics (all lanes redundantly, identical) --------
        const float sol0 = S[0][0] + b30;
        const float phi  = expf(-sol0);

        const float D10 = S[1][0], D20 = S[2][0], Dt0 = S[3][0];
        const float e11 = S[1][1];                    // d1 u1
        const float e22 = S[2][2];                    // d2 u2
        const float e12 = 0.5f * (S[1][2] + S[2][1]); // (d1 u2 + d2 u1)/2

        const float S11_0 = S[4][0], S11_1 = S[4][1], S11_2 = S[4][2];
        const float S12_1 = S[5][1], S12_2 = S[5][2];
        const float S22_0 = S[6][0], S22_1 = S[6][1], S22_2 = S[6][2];

        const float tr  = e11 + e22;
        const float trp = fmaxf(tr, 0.f);
        const float dd  = e11 - e22;
        const float psi = 0.5f * (LAM_ + MU_) * trp * trp
                        + MU_ * (0.5f * dd * dd + 2.f * e12 * e12);

        // div sigma_j = (mu+lam) d_j(div u) + mu Lap(u_j)
        const float div1 = (MU_ + LAM_) * (S11_1 + S12_2) + MU_ * (S11_1 + S22_1);
        const float div2 = (MU_ + LAM_) * (S12_1 + S22_2) + MU_ * (S11_2 + S22_2);

        const float omphi = 1.f - phi;
        const float fac   = omphi * omphi;
        const float resS  = fac * (fabsf(div1) + fabsf(div2));

        const float lap_phi = phi * (D10 * D10 + D20 * D20 - (S11_0 + S22_0));
        const float resP    = GC_ * (phi / LEN_ - LEN_ * lap_phi) - 2.f * omphi * psi;

        const float irr = fmaxf(phi * Dt0, 0.f);  // relu(-dphi/dt)

        lsS = fmaf(resS, resS, lsS);
        lsP = fmaf(resP, resP, lsP);
        lsI += irr;
    }

    // ---------------- deterministic block reduction --------------------------
    if (lane == 0) {
        red[warp][0] = lsS;
        red[warp][1] = lsP;
        red[warp][2] = lsI;
    }
    __syncthreads();
    if (threadIdx.x < 3) {
        float s = 0.f;
        #pragma unroll
        for (int w = 0; w < NWARP; w++) s += red[w][threadIdx.x];
        g_partials[blockIdx.x * 3 + threadIdx.x] = s;
    }
    __syncthreads();

    // Last block to finish performs the final reduction (no 2nd launch).
    if (threadIdx.x == 0) {
        __threadfence();
        const unsigned int c = atomicAdd(&g_ticket, 1u);
        s_last = (c == (unsigned int)(NBLK - 1)) ? 1u : 0u;
    }
    __syncthreads();
    if (s_last) {
        __threadfence();  // acquire: all other blocks' partials visible
        if (warp < 3) {
            float s = 0.f;
            for (int b = lane; b < NBLK; b += 32)
                s += g_partials[b * 3 + warp];
            #pragma unroll
            for (int off = 16; off > 0; off >>= 1)
                s += __shfl_xor_sync(0xFFFFFFFFu, s, off);
            if (lane == 0)
                out[warp] = s * (1.f / (float)N_PTS);
        }
        if (threadIdx.x == 0)
            g_ticket = 0u;  // reset for the next graph replay
    }
}

extern "C" void kernel_launch(void* const* d_in, const int* in_sizes, int n_in,
                              void* d_out, int out_size) {
    const float* x  = (const float*)d_in[0];
    const float* t  = (const float*)d_in[1];
    const float* W0 = (const float*)d_in[2];
    const float* b0 = (const float*)d_in[3];
    const float* W1 = (const float*)d_in[4];
    const float* b1 = (const float*)d_in[5];
    const float* W2 = (const float*)d_in[6];
    const float* b2 = (const float*)d_in[7];
    const float* W3 = (const float*)d_in[8];
    const float* b3 = (const float*)d_in[9];

    cudaFuncSetAttribute(pinn_main, cudaFuncAttributeMaxDynamicSharedMemorySize,
                         SMEM_BYTES);

    pinn_main<<<NBLK, NTHREADS, SMEM_BYTES>>>(x, t, W0, b0, W1, b1, W2, b2, W3, b3,
                                              (float*)d_out);
}

// round 9
// speedup vs baseline: 1.0950x; 1.0950x over previous
#include <cuda_runtime.h>
#include <math.h>

// ---------------------------------------------------------------------------
// PINN phase-field fracture residual losses on GB300 (sm_103a).
//
// Per point (x1,x2,t): forward MLP 3->128->128->128->3 (tanh) with
// forward-mode tangents along (x1, x2, t) and forward-over-forward second
// tangents along (x1x1, x1x2, x2x2). 7 vectors of width 128 per point.
//
//   value:  h  = tanh(z)
//   first:  d  = (1-h^2) * zd
//   second: s  = (1-h^2) * zs - 2 h (1-h^2) * zd_v * zd_w
//
// Physics:
//   div sigma_j = (mu+lam) * d_j(div u) + mu * Lap(u_j)
//   lap phi     = phi * (|grad s0|^2 - Lap s0),  phi = exp(-s0)
//   dphi/dt     = -phi * dt(s0)
//
// Mainloop: channel-pair packed fma.rn.f32x2 (R5 structure — best measured).
// 20 warps/CTA (5/SMSP) for latency hiding; 1 CTA/SM.
// Final cross-block reduction by last block (atomic ticket), single launch.
// ---------------------------------------------------------------------------

namespace {
constexpr int N_PTS   = 8192;
constexpr int HID     = 128;
constexpr int NVEC    = 7;       // h, d1, d2, dt, s11, s12, s22
constexpr int NBLK    = 148;     // one CTA per SM
constexpr int NWARP   = 20;      // 5 warps per SMSP
constexpr int NTHREADS = NWARP * 32;           // 640
constexpr int NWARP_TOT = NBLK * NWARP;        // 2960

constexpr float MU_  = 80.77f;
constexpr float LAM_ = 121.15f;
constexpr float GC_  = 2.7e-3f;
constexpr float LEN_ = 0.015f;

constexpr int SMEM_FLOATS = 2 * HID * HID + NWARP * NVEC * HID;  // 50688
constexpr int SMEM_BYTES  = SMEM_FLOATS * 4;                     // 202752
}

__device__ float g_partials[NBLK * 3];
__device__ unsigned int g_ticket;   // zero-init; reset by last block each call

#define F4C(v, c) ((c) == 0 ? (v).x : (c) == 1 ? (v).y : (c) == 2 ? (v).z : (v).w)

__device__ __forceinline__ unsigned long long pack2(float a, float b) {
    unsigned long long r;
    asm("mov.b64 %0, {%1, %2};" : "=l"(r) : "f"(a), "f"(b));
    return r;
}
__device__ __forceinline__ void fma2(unsigned long long& d,
                                     unsigned long long a, unsigned long long b) {
    asm("fma.rn.f32x2 %0, %1, %2, %0;" : "+l"(d) : "l"(a), "l"(b));
}
__device__ __forceinline__ float2 unpack2(unsigned long long v) {
    float2 r;
    asm("mov.b64 {%0, %1}, %2;" : "=f"(r.x), "=f"(r.y) : "l"(v));
    return r;
}

__global__ void __launch_bounds__(NTHREADS, 1)
pinn_main(const float* __restrict__ x,  const float* __restrict__ t,
          const float* __restrict__ W0, const float* __restrict__ b0,
          const float* __restrict__ W1, const float* __restrict__ b1,
          const float* __restrict__ W2, const float* __restrict__ b2,
          const float* __restrict__ W3, const float* __restrict__ b3,
          float* __restrict__ out)
{
    extern __shared__ float smem[];
    float* Wsh  = smem;                  // [2][128*128]
    float* Vall = smem + 2 * HID * HID;  // [NWARP][NVEC][128]
    __shared__ float red[NWARP][3];
    __shared__ unsigned int s_last;

    // Cooperative load of hidden-layer weights into SMEM.
    {
        const float4* s1 = reinterpret_cast<const float4*>(W1);
        const float4* s2 = reinterpret_cast<const float4*>(W2);
        float4* d1 = reinterpret_cast<float4*>(Wsh);
        float4* d2 = reinterpret_cast<float4*>(Wsh + HID * HID);
        for (int i = threadIdx.x; i < HID * HID / 4; i += NTHREADS) {
            d1[i] = s1[i];
            d2[i] = s2[i];
        }
    }
    __syncthreads();

    const int warp = threadIdx.x >> 5;
    const int lane = threadIdx.x & 31;
    const int j0   = lane * 4;           // this lane owns channels j0..j0+3
    float* V = Vall + warp * (NVEC * HID);

    const float b30 = b3[0];

    float lsS = 0.f, lsP = 0.f, lsI = 0.f;

    // Transposed warp->point map: extra points spread across all SMs/SMSPs.
    const int wg = blockIdx.x + NBLK * warp;

    for (int p = wg; p < N_PTS; p += NWARP_TOT) {
        const float x1 = x[2 * p + 0];
        const float x2 = x[2 * p + 1];
        const float tt = t[p];

        __syncwarp();  // previous iteration's V reads done before overwrite

        // ---------------- layer 0 (3 -> 128), input is linear in coords ----
        // W0/b0 reloaded each point (L1-resident): keeps them out of the
        // mainloop register live-set.
        {
            const float4 w00 = *reinterpret_cast<const float4*>(W0 + 0 * HID + j0);
            const float4 w01 = *reinterpret_cast<const float4*>(W0 + 1 * HID + j0);
            const float4 w02 = *reinterpret_cast<const float4*>(W0 + 2 * HID + j0);
            const float4 bb0 = *reinterpret_cast<const float4*>(b0 + j0);
            #pragma unroll
            for (int c = 0; c < 4; c++) {
                const float a0 = F4C(w00, c);
                const float a1 = F4C(w01, c);
                const float a2 = F4C(w02, c);
                const float z  = fmaf(x1, a0, fmaf(x2, a1, fmaf(tt, a2, F4C(bb0, c))));
                const float h  = tanhf(z);
                const float g  = 1.f - h * h;
                const float m2 = -2.f * h * g;
                V[0 * HID + j0 + c] = h;
                V[1 * HID + j0 + c] = g * a0;       // d/dx1
                V[2 * HID + j0 + c] = g * a1;       // d/dx2
                V[3 * HID + j0 + c] = g * a2;       // d/dt
                V[4 * HID + j0 + c] = m2 * a0 * a0; // d2/dx1dx1
                V[5 * HID + j0 + c] = m2 * a0 * a1; // d2/dx1dx2
                V[6 * HID + j0 + c] = m2 * a1 * a1; // d2/dx2dx2
            }
        }
        __syncwarp();

        // ---------------- hidden layers 1 & 2 (128 -> 128) ------------------
        #pragma unroll
        for (int L = 0; L < 2; L++) {
            const float* W = Wsh + L * HID * HID;

            unsigned long long accL[NVEC], accH[NVEC];
            #pragma unroll
            for (int v = 0; v < NVEC; v++) { accL[v] = 0ull; accH[v] = 0ull; }

            #pragma unroll 2
            for (int k = 0; k < HID; k += 4) {
                // Weight rows: conflict-free 16B/lane. V entries: warp-broadcast.
                const ulonglong2 wr0 =
                    *reinterpret_cast<const ulonglong2*>(W + (k + 0) * HID + j0);
                const ulonglong2 wr1 =
                    *reinterpret_cast<const ulonglong2*>(W + (k + 1) * HID + j0);
                const ulonglong2 wr2 =
                    *reinterpret_cast<const ulonglong2*>(W + (k + 2) * HID + j0);
                const ulonglong2 wr3 =
                    *reinterpret_cast<const ulonglong2*>(W + (k + 3) * HID + j0);
                const float* Vk = V + k;
                #pragma unroll
                for (int v = 0; v < NVEC; v++) {
                    const float4 vv = *reinterpret_cast<const float4*>(Vk + v * HID);
                    unsigned long long s;
                    s = pack2(vv.x, vv.x); fma2(accL[v], s, wr0.x); fma2(accH[v], s, wr0.y);
                    s = pack2(vv.y, vv.y); fma2(accL[v], s, wr1.x); fma2(accH[v], s, wr1.y);
                    s = pack2(vv.z, vv.z); fma2(accL[v], s, wr2.x); fma2(accH[v], s, wr2.y);
                    s = pack2(vv.w, vv.w); fma2(accL[v], s, wr3.x); fma2(accH[v], s, wr3.y);
                }
            }

            // Unpack accumulators to per-channel scalars.
            float accf[NVEC][4];
            #pragma unroll
            for (int v = 0; v < NVEC; v++) {
                const float2 lo = unpack2(accL[v]);
                const float2 hi = unpack2(accH[v]);
                accf[v][0] = lo.x; accf[v][1] = lo.y;
                accf[v][2] = hi.x; accf[v][3] = hi.y;
            }

            // Bias reloaded here (L1-resident), not pinned across the loop.
            const float4 bb = (L == 0)
                ? *reinterpret_cast<const float4*>(b1 + j0)
                : *reinterpret_cast<const float4*>(b2 + j0);
            __syncwarp();  // everyone done reading V for this layer
            #pragma unroll
            for (int c = 0; c < 4; c++) {
                const float zh  = accf[0][c] + F4C(bb, c);
                const float h   = tanhf(zh);
                const float g   = 1.f - h * h;
                const float zd1 = accf[1][c];
                const float zd2 = accf[2][c];
                const float zdt = accf[3][c];
                const float m2  = -2.f * h * g;
                V[0 * HID + j0 + c] = h;
                V[1 * HID + j0 + c] = g * zd1;
                V[2 * HID + j0 + c] = g * zd2;
                V[3 * HID + j0 + c] = g * zdt;
                V[4 * HID + j0 + c] = fmaf(m2 * zd1, zd1, g * accf[4][c]);
                V[5 * HID + j0 + c] = fmaf(m2 * zd1, zd2, g * accf[5][c]);
                V[6 * HID + j0 + c] = fmaf(m2 * zd2, zd2, g * accf[6][c]);
            }
            __syncwarp();
        }

        // ---------------- output layer (128 -> 3) + warp reduction ----------
        // W3 rows loaded at point of use (L1-hit) to keep them out of the
        // persistent register live-set.
        float S[NVEC][3];
        #pragma unroll
        for (int v = 0; v < NVEC; v++)
            S[v][0] = S[v][1] = S[v][2] = 0.f;

        #pragma unroll
        for (int m = 0; m < 4; m++) {
            const int k = lane + 32 * m;
            const float wk0 = __ldg(W3 + k * 3 + 0);
            const float wk1 = __ldg(W3 + k * 3 + 1);
            const float wk2 = __ldg(W3 + k * 3 + 2);
            #pragma unroll
            for (int v = 0; v < NVEC; v++) {
                const float vk = V[v * HID + k];
                S[v][0] = fmaf(vk, wk0, S[v][0]);
                S[v][1] = fmaf(vk, wk1, S[v][1]);
                S[v][2] = fmaf(vk, wk2, S[v][2]);
            }
        }
        #pragma unroll
        for (int v = 0; v < NVEC; v++)
            #pragma unroll
            for (int o = 0; o < 3; o++)
                #pragma unroll
                for (int off = 16; off > 0; off >>= 1)
                    S[v][o] += __shfl_xor_sync(0xFFFFFFFFu, S[v][o], off);

        // ---------------- physics (all lanes redundantly, identical) --------
        const float sol0 = S[0][0] + b30;
        const float phi  = expf(-sol0);

        const float D10 = S[1][0], D20 = S[2][0], Dt0 = S[3][0];
        const float e11 = S[1][1];                    // d1 u1
        const float e22 = S[2][2];                    // d2 u2
        const float e12 = 0.5f * (S[1][2] + S[2][1]); // (d1 u2 + d2 u1)/2

        const float S11_0 = S[4][0], S11_1 = S[4][1], S11_2 = S[4][2];
        const float S12_1 = S[5][1], S12_2 = S[5][2];
        const float S22_0 = S[6][0], S22_1 = S[6][1], S22_2 = S[6][2];

        const float tr  = e11 + e22;
        const float trp = fmaxf(tr, 0.f);
        const float dd  = e11 - e22;
        const float psi = 0.5f * (LAM_ + MU_) * trp * trp
                        + MU_ * (0.5f * dd * dd + 2.f * e12 * e12);

        // div sigma_j = (mu+lam) d_j(div u) + mu Lap(u_j)
        const float div1 = (MU_ + LAM_) * (S11_1 + S12_2) + MU_ * (S11_1 + S22_1);
        const float div2 = (MU_ + LAM_) * (S12_1 + S22_2) + MU_ * (S11_2 + S22_2);

        const float omphi = 1.f - phi;
        const float fac   = omphi * omphi;
        const float resS  = fac * (fabsf(div1) + fabsf(div2));

        const float lap_phi = phi * (D10 * D10 + D20 * D20 - (S11_0 + S22_0));
        const float resP    = GC_ * (phi / LEN_ - LEN_ * lap_phi) - 2.f * omphi * psi;

        const float irr = fmaxf(phi * Dt0, 0.f);  // relu(-dphi/dt)

        lsS = fmaf(resS, resS, lsS);
        lsP = fmaf(resP, resP, lsP);
        lsI += irr;
    }

    // ---------------- deterministic block reduction --------------------------
    if (lane == 0) {
        red[warp][0] = lsS;
        red[warp][1] = lsP;
        red[warp][2] = lsI;
    }
    __syncthreads();
    if (threadIdx.x < 3) {
        float s = 0.f;
        #pragma unroll
        for (int w = 0; w < NWARP; w++) s += red[w][threadIdx.x];
        g_partials[blockIdx.x * 3 + threadIdx.x] = s;
    }
    __syncthreads();

    // Last block to finish performs the final reduction (no 2nd launch).
    if (threadIdx.x == 0) {
        __threadfence();
        const unsigned int c = atomicAdd(&g_ticket, 1u);
        s_last = (c == (unsigned int)(NBLK - 1)) ? 1u : 0u;
    }
    __syncthreads();
    if (s_last) {
        __threadfence();  // acquire: all other blocks' partials visible
        if (warp < 3) {
            float s = 0.f;
            for (int b = lane; b < NBLK; b += 32)
                s += g_partials[b * 3 + warp];
            #pragma unroll
            for (int off = 16; off > 0; off >>= 1)
                s += __shfl_xor_sync(0xFFFFFFFFu, s, off);
            if (lane == 0)
                out[warp] = s * (1.f / (float)N_PTS);
        }
        if (threadIdx.x == 0)
            g_ticket = 0u;  // reset for the next graph replay
    }
}

extern "C" void kernel_launch(void* const* d_in, const int* in_sizes, int n_in,
                              void* d_out, int out_size) {
    const float* x  = (const float*)d_in[0];
    const float* t  = (const float*)d_in[1];
    const float* W0 = (const float*)d_in[2];
    const float* b0 = (const float*)d_in[3];
    const float* W1 = (const float*)d_in[4];
    const float* b1 = (const float*)d_in[5];
    const float* W2 = (const float*)d_in[6];
    const float* b2 = (const float*)d_in[7];
    const float* W3 = (const float*)d_in[8];
    const float* b3 = (const float*)d_in[9];

    cudaFuncSetAttribute(pinn_main, cudaFuncAttributeMaxDynamicSharedMemorySize,
                         SMEM_BYTES);

    pinn_main<<<NBLK, NTHREADS, SMEM_BYTES>>>(x, t, W0, b0, W1, b1, W2, b2, W3, b3,
                                              (float*)d_out);
}

// round 15
// speedup vs baseline: 1.1434x; 1.0442x over previous
#include <cuda_runtime.h>
#include <math.h>

// ---------------------------------------------------------------------------
// PINN phase-field fracture residual losses on GB300 (sm_103a).
//
// Per point (x1,x2,t): forward MLP 3->128->128->128->3 (tanh) with
// forward-mode tangents along (x1, x2, t) and forward-over-forward second
// tangents along (x1x1, x1x2, x2x2). 7 vectors of width 128 per point.
//
// Mainloop: channel-pair packed fma.rn.f32x2. This revision orders the chunk
// k-outer / v-inner so same-accumulator FFMA2 reuse distance is ~21
// instructions (was 2), keeping the FMA pipe fed without relying on ptxas
// reordering. 16 warps/CTA (R5 config — best measured).
// Final cross-block reduction by last block (atomic ticket), single launch.
// ---------------------------------------------------------------------------

namespace {
constexpr int N_PTS   = 8192;
constexpr int HID     = 128;
constexpr int NVEC    = 7;       // h, d1, d2, dt, s11, s12, s22
constexpr int NBLK    = 148;     // one CTA per SM
constexpr int NWARP   = 16;
constexpr int NTHREADS = NWARP * 32;           // 512
constexpr int NWARP_TOT = NBLK * NWARP;        // 2368

constexpr float MU_  = 80.77f;
constexpr float LAM_ = 121.15f;
constexpr float GC_  = 2.7e-3f;
constexpr float LEN_ = 0.015f;

constexpr int SMEM_FLOATS = 2 * HID * HID + NWARP * NVEC * HID;  // 47104
constexpr int SMEM_BYTES  = SMEM_FLOATS * 4;                     // 188416
}

__device__ float g_partials[NBLK * 3];
__device__ unsigned int g_ticket;   // zero-init; reset by last block each call

#define F4C(v, c) ((c) == 0 ? (v).x : (c) == 1 ? (v).y : (c) == 2 ? (v).z : (v).w)

__device__ __forceinline__ unsigned long long pack2(float a, float b) {
    unsigned long long r;
    asm("mov.b64 %0, {%1, %2};" : "=l"(r) : "f"(a), "f"(b));
    return r;
}
__device__ __forceinline__ void fma2(unsigned long long& d,
                                     unsigned long long a, unsigned long long b) {
    asm("fma.rn.f32x2 %0, %1, %2, %0;" : "+l"(d) : "l"(a), "l"(b));
}
__device__ __forceinline__ float2 unpack2(unsigned long long v) {
    float2 r;
    asm("mov.b64 {%0, %1}, %2;" : "=f"(r.x), "=f"(r.y) : "l"(v));
    return r;
}

__global__ void __launch_bounds__(NTHREADS, 1)
pinn_main(const float* __restrict__ x,  const float* __restrict__ t,
          const float* __restrict__ W0, const float* __restrict__ b0,
          const float* __restrict__ W1, const float* __restrict__ b1,
          const float* __restrict__ W2, const float* __restrict__ b2,
          const float* __restrict__ W3, const float* __restrict__ b3,
          float* __restrict__ out)
{
    extern __shared__ float smem[];
    float* Wsh  = smem;                  // [2][128*128]
    float* Vall = smem + 2 * HID * HID;  // [NWARP][NVEC][128]
    __shared__ float red[NWARP][3];
    __shared__ unsigned int s_last;

    // Cooperative load of hidden-layer weights into SMEM.
    {
        const float4* s1 = reinterpret_cast<const float4*>(W1);
        const float4* s2 = reinterpret_cast<const float4*>(W2);
        float4* d1 = reinterpret_cast<float4*>(Wsh);
        float4* d2 = reinterpret_cast<float4*>(Wsh + HID * HID);
        for (int i = threadIdx.x; i < HID * HID / 4; i += NTHREADS) {
            d1[i] = s1[i];
            d2[i] = s2[i];
        }
    }
    __syncthreads();

    const int warp = threadIdx.x >> 5;
    const int lane = threadIdx.x & 31;
    const int j0   = lane * 4;           // this lane owns channels j0..j0+3
    float* V = Vall + warp * (NVEC * HID);

    float w3r[4][3];
    #pragma unroll
    for (int m = 0; m < 4; m++) {
        const int k = lane + 32 * m;
        w3r[m][0] = W3[k * 3 + 0];
        w3r[m][1] = W3[k * 3 + 1];
        w3r[m][2] = W3[k * 3 + 2];
    }
    const float b30 = b3[0];

    float lsS = 0.f, lsP = 0.f, lsI = 0.f;

    // Transposed warp->point map: extra points spread across all SMs/SMSPs.
    const int wg = blockIdx.x + NBLK * warp;

    for (int p = wg; p < N_PTS; p += NWARP_TOT) {
        const float x1 = x[2 * p + 0];
        const float x2 = x[2 * p + 1];
        const float tt = t[p];

        __syncwarp();  // previous iteration's V reads done before overwrite

        // ---------------- layer 0 (3 -> 128), input is linear in coords ----
        {
            const float4 w00 = *reinterpret_cast<const float4*>(W0 + 0 * HID + j0);
            const float4 w01 = *reinterpret_cast<const float4*>(W0 + 1 * HID + j0);
            const float4 w02 = *reinterpret_cast<const float4*>(W0 + 2 * HID + j0);
            const float4 bb0 = *reinterpret_cast<const float4*>(b0 + j0);
            #pragma unroll
            for (int c = 0; c < 4; c++) {
                const float a0 = F4C(w00, c);
                const float a1 = F4C(w01, c);
                const float a2 = F4C(w02, c);
                const float z  = fmaf(x1, a0, fmaf(x2, a1, fmaf(tt, a2, F4C(bb0, c))));
                const float h  = tanhf(z);
                const float g  = 1.f - h * h;
                const float m2 = -2.f * h * g;
                V[0 * HID + j0 + c] = h;
                V[1 * HID + j0 + c] = g * a0;       // d/dx1
                V[2 * HID + j0 + c] = g * a1;       // d/dx2
                V[3 * HID + j0 + c] = g * a2;       // d/dt
                V[4 * HID + j0 + c] = m2 * a0 * a0; // d2/dx1dx1
                V[5 * HID + j0 + c] = m2 * a0 * a1; // d2/dx1dx2
                V[6 * HID + j0 + c] = m2 * a1 * a1; // d2/dx2dx2
            }
        }
        __syncwarp();

        // ---------------- hidden layers 1 & 2 (128 -> 128) ------------------
        #pragma unroll
        for (int L = 0; L < 2; L++) {
            const float* W = Wsh + L * HID * HID;

            unsigned long long accL[NVEC], accH[NVEC];
            #pragma unroll
            for (int v = 0; v < NVEC; v++) { accL[v] = 0ull; accH[v] = 0ull; }

            #pragma unroll 2
            for (int k = 0; k < HID; k += 4) {
                // Weight rows: conflict-free 16B/lane. V entries: warp-broadcast.
                const ulonglong2 wr0 =
                    *reinterpret_cast<const ulonglong2*>(W + (k + 0) * HID + j0);
                const ulonglong2 wr1 =
                    *reinterpret_cast<const ulonglong2*>(W + (k + 1) * HID + j0);
                const ulonglong2 wr2 =
                    *reinterpret_cast<const ulonglong2*>(W + (k + 2) * HID + j0);
                const ulonglong2 wr3 =
                    *reinterpret_cast<const ulonglong2*>(W + (k + 3) * HID + j0);
                const float* Vk = V + k;

                // Hoist all 7 V fragments for this chunk.
                float4 vv[NVEC];
                #pragma unroll
                for (int v = 0; v < NVEC; v++)
                    vv[v] = *reinterpret_cast<const float4*>(Vk + v * HID);

                // k-outer / v-inner: consecutive FFMA2s touch DIFFERENT
                // accumulators (reuse distance ~21 insts, lat 4 covered).
                #pragma unroll
                for (int v = 0; v < NVEC; v++) {
                    const unsigned long long s = pack2(vv[v].x, vv[v].x);
                    fma2(accL[v], s, wr0.x); fma2(accH[v], s, wr0.y);
                }
                #pragma unroll
                for (int v = 0; v < NVEC; v++) {
                    const unsigned long long s = pack2(vv[v].y, vv[v].y);
                    fma2(accL[v], s, wr1.x); fma2(accH[v], s, wr1.y);
                }
                #pragma unroll
                for (int v = 0; v < NVEC; v++) {
                    const unsigned long long s = pack2(vv[v].z, vv[v].z);
                    fma2(accL[v], s, wr2.x); fma2(accH[v], s, wr2.y);
                }
                #pragma unroll
                for (int v = 0; v < NVEC; v++) {
                    const unsigned long long s = pack2(vv[v].w, vv[v].w);
                    fma2(accL[v], s, wr3.x); fma2(accH[v], s, wr3.y);
                }
            }

            // Unpack accumulators to per-channel scalars.
            float accf[NVEC][4];
            #pragma unroll
            for (int v = 0; v < NVEC; v++) {
                const float2 lo = unpack2(accL[v]);
                const float2 hi = unpack2(accH[v]);
                accf[v][0] = lo.x; accf[v][1] = lo.y;
                accf[v][2] = hi.x; accf[v][3] = hi.y;
            }

            const float4 bb = (L == 0)
                ? *reinterpret_cast<const float4*>(b1 + j0)
                : *reinterpret_cast<const float4*>(b2 + j0);
            __syncwarp();  // everyone done reading V for this layer
            #pragma unroll
            for (int c = 0; c < 4; c++) {
                const float zh  = accf[0][c] + F4C(bb, c);
                const float h   = tanhf(zh);
                const float g   = 1.f - h * h;
                const float zd1 = accf[1][c];
                const float zd2 = accf[2][c];
                const float zdt = accf[3][c];
                const float m2  = -2.f * h * g;
                V[0 * HID + j0 + c] = h;
                V[1 * HID + j0 + c] = g * zd1;
                V[2 * HID + j0 + c] = g * zd2;
                V[3 * HID + j0 + c] = g * zdt;
                V[4 * HID + j0 + c] = fmaf(m2 * zd1, zd1, g * accf[4][c]);
                V[5 * HID + j0 + c] = fmaf(m2 * zd1, zd2, g * accf[5][c]);
                V[6 * HID + j0 + c] = fmaf(m2 * zd2, zd2, g * accf[6][c]);
            }
            __syncwarp();
        }

        // ---------------- output layer (128 -> 3) + warp reduction ----------
        float S[NVEC][3];
        #pragma unroll
        for (int v = 0; v < NVEC; v++)
            S[v][0] = S[v][1] = S[v][2] = 0.f;

        #pragma unroll
        for (int m = 0; m < 4; m++) {
            const int k = lane + 32 * m;
            #pragma unroll
            for (int v = 0; v < NVEC; v++) {
                const float vk = V[v * HID + k];
                S[v][0] = fmaf(vk, w3r[m][0], S[v][0]);
                S[v][1] = fmaf(vk, w3r[m][1], S[v][1]);
                S[v][2] = fmaf(vk, w3r[m][2], S[v][2]);
            }
        }
        #pragma unroll
        for (int v = 0; v < NVEC; v++)
            #pragma unroll
            for (int o = 0; o < 3; o++)
                #pragma unroll
                for (int off = 16; off > 0; off >>= 1)
                    S[v][o] += __shfl_xor_sync(0xFFFFFFFFu, S[v][o], off);

        // ---------------- physics (all lanes redundantly, identical) --------
        const float sol0 = S[0][0] + b30;
        const float phi  = expf(-sol0);

        const float D10 = S[1][0], D20 = S[2][0], Dt0 = S[3][0];
        const float e11 = S[1][1];                    // d1 u1
        const float e22 = S[2][2];                    // d2 u2
        const float e12 = 0.5f * (S[1][2] + S[2][1]); // (d1 u2 + d2 u1)/2

        const float S11_0 = S[4][0], S11_1 = S[4][1], S11_2 = S[4][2];
        const float S12_1 = S[5][1], S12_2 = S[5][2];
        const float S22_0 = S[6][0], S22_1 = S[6][1], S22_2 = S[6][2];

        const float tr  = e11 + e22;
        const float trp = fmaxf(tr, 0.f);
        const float dd  = e11 - e22;
        const float psi = 0.5f * (LAM_ + MU_) * trp * trp
                        + MU_ * (0.5f * dd * dd + 2.f * e12 * e12);

        // div sigma_j = (mu+lam) d_j(div u) + mu Lap(u_j)
        const float div1 = (MU_ + LAM_) * (S11_1 + S12_2) + MU_ * (S11_1 + S22_1);
        const float div2 = (MU_ + LAM_) * (S12_1 + S22_2) + MU_ * (S11_2 + S22_2);

        const float omphi = 1.f - phi;
        const float fac   = omphi * omphi;
        const float resS  = fac * (fabsf(div1) + fabsf(div2));

        const float lap_phi = phi * (D10 * D10 + D20 * D20 - (S11_0 + S22_0));
        const float resP    = GC_ * (phi / LEN_ - LEN_ * lap_phi) - 2.f * omphi * psi;

        const float irr = fmaxf(phi * Dt0, 0.f);  // relu(-dphi/dt)

        lsS = fmaf(resS, resS, lsS);
        lsP = fmaf(resP, resP, lsP);
        lsI += irr;
    }

    // ---------------- deterministic block reduction --------------------------
    if (lane == 0) {
        red[warp][0] = lsS;
        red[warp][1] = lsP;
        red[warp][2] = lsI;
    }
    __syncthreads();
    if (threadIdx.x < 3) {
        float s = 0.f;
        #pragma unroll
        for (int w = 0; w < NWARP; w++) s += red[w][threadIdx.x];
        g_partials[blockIdx.x * 3 + threadIdx.x] = s;
    }
    __syncthreads();

    // Last block to finish performs the final reduction (no 2nd launch).
    if (threadIdx.x == 0) {
        __threadfence();
        const unsigned int c = atomicAdd(&g_ticket, 1u);
        s_last = (c == (unsigned int)(NBLK - 1)) ? 1u : 0u;
    }
    __syncthreads();
    if (s_last) {
        __threadfence();  // acquire: all other blocks' partials visible
        if (warp < 3) {
            float s = 0.f;
            for (int b = lane; b < NBLK; b += 32)
                s += g_partials[b * 3 + warp];
            #pragma unroll
            for (int off = 16; off > 0; off >>= 1)
                s += __shfl_xor_sync(0xFFFFFFFFu, s, off);
            if (lane == 0)
                out[warp] = s * (1.f / (float)N_PTS);
        }
        if (threadIdx.x == 0)
            g_ticket = 0u;  // reset for the next graph replay
    }
}

extern "C" void kernel_launch(void* const* d_in, const int* in_sizes, int n_in,
                              void* d_out, int out_size) {
    const float* x  = (const float*)d_in[0];
    const float* t  = (const float*)d_in[1];
    const float* W0 = (const float*)d_in[2];
    const float* b0 = (const float*)d_in[3];
    const float* W1 = (const float*)d_in[4];
    const float* b1 = (const float*)d_in[5];
    const float* W2 = (const float*)d_in[6];
    const float* b2 = (const float*)d_in[7];
    const float* W3 = (const float*)d_in[8];
    const float* b3 = (const float*)d_in[9];

    cudaFuncSetAttribute(pinn_main, cudaFuncAttributeMaxDynamicSharedMemorySize,
                         SMEM_BYTES);

    pinn_main<<<NBLK, NTHREADS, SMEM_BYTES>>>(x, t, W0, b0, W1, b1, W2, b2, W3, b3,
                                              (float*)d_out);
}